// round 11
// baseline (speedup 1.0000x reference)
#include <cuda_runtime.h>
#include <math_constants.h>
#include <cstdint>

#define NROWS 100000
#define DIM   1024
#define RNUM  64

#define SEG        1024
#define NSEG_CKPT  97          // boundaries at rows 1024..99328

// colsum pipeline: 32 blocks x 32 cols, 512-row tiles, 3-stage cp.async ring
#define CS_BLOCKS 32
#define CS_COLS   32
#define CS_T      512
#define CS_S      3
#define CS_SMEM   (CS_S * CS_T * CS_COLS * 4)   // 192 KB dynamic

// dots: 256 rows per block, 32-col chunks, double-buffered
#define DR   256
#define DCH  32
#define DBLK ((NROWS + DR - 1) / DR)    // 391

// -------- scratch (no allocations allowed) --------
__device__ float g_ckpt[NSEG_CKPT][DIM];  // chain state after rows [0,(s+1)*SEG)
__device__ float g_m[DIM];
__device__ float g_taken[NROWS];
__device__ int   g_takenList[RNUM];       // sorted ascending, distinct taken rows
__device__ int   g_nTaken;
__device__ int   g_remaining;
__device__ int   g_restartSeg;            // first segment whose chain changed
__device__ unsigned long long g_best;     // packed (enc(score) << 32) | ~idx
__device__ int   g_sel[RNUM];
__device__ int   g_selSorted[RNUM];

// monotone float encoding; ties -> smaller idx wins via ~idx in low bits
__device__ __forceinline__ unsigned long long pack_key(float s, int idx) {
    unsigned b = __float_as_uint(s);
    b = (b & 0x80000000u) ? ~b : (b | 0x80000000u);
    return ((unsigned long long)b << 32) | (unsigned)(0xffffffffu - (unsigned)idx);
}

// -------- init (graph replays must fully reset state) --------
__global__ void init_kernel() {
    int i = blockIdx.x * blockDim.x + threadIdx.x;
    if (i < NROWS) g_taken[i] = 0.0f;
    if (i == 0) { g_remaining = NROWS; g_nTaken = 0; g_restartSeg = 0; g_best = 0ull; }
}

__device__ __forceinline__ void cp_async16(uint32_t saddr, const float* gptr) {
    asm volatile("cp.async.ca.shared.global [%0], [%1], 16;" :: "r"(saddr), "l"(gptr));
}

// producers (threads 32..255): issue one 512-row x 32-col tile (4096 x 16B)
__device__ __forceinline__ void cs_issue(const float* __restrict__ x, uint32_t bufAddr,
                                         int rStart, int ti, int colBase, int t) {
    int r0 = rStart + ti * CS_T;
    int st = ti % CS_S;
    uint32_t stBase = bufAddr + (uint32_t)(st * CS_T * CS_COLS * 4);
    int p = t - 32;                       // 0..223
    for (int op = p; op < CS_T * 8; op += 224) {
        int row = op >> 3;
        int ch  = op & 7;
        int gr = r0 + row;
        if (gr < NROWS)
            cp_async16(stBase + (uint32_t)((row * CS_COLS + ch * 4) * 4),
                       x + (size_t)gr * DIM + colBase + ch * 4);
    }
}

// -------- colsum: bit-exact sequential fadd chain per column (validated),
// warp-specialized: warps 1-7 produce via cp.async ring, warp 0 = 32 chains. --
__global__ void __launch_bounds__(256) colsum_kernel(const float* __restrict__ x) {
    extern __shared__ float buf[];               // [CS_S][CS_T][CS_COLS]
    __shared__ int sList[RNUM];
    __shared__ int sMeta[3];

    int t = threadIdx.x;
    if (t == 0) { sMeta[0] = g_nTaken; sMeta[1] = g_restartSeg; sMeta[2] = g_remaining; }
    __syncthreads();
    int sN = sMeta[0], sSeg = sMeta[1], sRem = sMeta[2];
    if (t < RNUM && t < sN) sList[t] = g_takenList[t];
    __syncthreads();

    int colBase = blockIdx.x * CS_COLS;
    int rStart = sSeg << 10;
    int ntiles = (NROWS - rStart + CS_T - 1) / CS_T;   // >= 2 always (tail >= 672 rows)

    uint32_t bufAddr = (uint32_t)__cvta_generic_to_shared(buf);
    bool producer = (t >= 32);

    // prologue: tiles 0..1 in flight
#pragma unroll
    for (int ti = 0; ti < CS_S - 1; ti++) {
        if (producer && ti < ntiles) cs_issue(x, bufAddr, rStart, ti, colBase, t);
        asm volatile("cp.async.commit_group;");
    }

    // consumer chain state (lanes 0..31 of warp 0)
    float acc = 0.0f;
    int p = 0, nxt = 0x7fffffff;
    if (t < CS_COLS) {
        if (sSeg > 0) acc = g_ckpt[sSeg - 1][colBase + t];
        while (p < sN && sList[p] < rStart) p++;
        nxt = (p < sN) ? sList[p] : 0x7fffffff;
    }

    for (int i = 0; i < ntiles; i++) {
        asm volatile("cp.async.wait_group 1;");  // tile i complete
        __syncthreads();
        if (producer && (i + CS_S - 1) < ntiles)
            cs_issue(x, bufAddr, rStart, i + CS_S - 1, colBase, t);
        asm volatile("cp.async.commit_group;");

        if (t < CS_COLS) {
            const float* s = buf + (i % CS_S) * CS_T * CS_COLS + t;
            int r0 = rStart + i * CS_T;
            int nr = min(CS_T, NROWS - r0);
            bool slow = (nr < CS_T) || (nxt < r0 + nr);
            if (!slow) {
                // pure chain, software-pipelined 16-row register batches
                float v0[16], v1[16];
#define LOADB(arr, b) { _Pragma("unroll") \
    for (int j = 0; j < 16; j++) arr[j] = s[(((b) << 4) + j) * CS_COLS]; }
#define CHAINB(arr) { _Pragma("unroll") \
    for (int j = 0; j < 16; j++) acc = __fadd_rn(acc, arr[j]); }
                LOADB(v0, 0)
#pragma unroll
                for (int b = 0; b < CS_T / 16; b++) {
                    if (b & 1) { if (b + 1 < CS_T / 16) LOADB(v0, b + 1) CHAINB(v1) }
                    else       { if (b + 1 < CS_T / 16) LOADB(v1, b + 1) CHAINB(v0) }
                }
                if (((r0 + CS_T) & (SEG - 1)) == 0)
                    g_ckpt[((r0 + CS_T) >> 10) - 1][colBase + t] = acc;
            } else {
                for (int j = 0; j < nr; j++) {
                    int r = r0 + j;
                    float v = s[j * CS_COLS];
                    if (r == nxt) { p++; nxt = (p < sN) ? sList[p] : 0x7fffffff; }
                    else acc = __fadd_rn(acc, v);
                    if (((r + 1) & (SEG - 1)) == 0)
                        g_ckpt[((r + 1) >> 10) - 1][colBase + t] = acc;
                }
            }
        }
        __syncthreads();
    }
    asm volatile("cp.async.wait_group 0;");
    if (t < CS_COLS)
        g_m[colBase + t] = __fdiv_rn(acc, (float)sRem);
}

// -------- dots + argmax: Eigen 4-chain FMA order (validated), double-buffered.
// Register-prefetch chunk cb+1 while computing cb; one atomicMax per block. ---
__global__ void __launch_bounds__(DR) dots_argmax_kernel(const float* __restrict__ x) {
    __shared__ float buf[2][DR][DCH + 1];    // stride 33: conflict-free
    __shared__ float ms[DIM];
    __shared__ float sSc[DR];
    __shared__ int   sIx[DR];

    int t = threadIdx.x;
    int row0 = blockIdx.x * DR;
    int row = row0 + t;
    bool valid = row < NROWS;

    for (int i = t; i < DIM; i += DR) ms[i] = g_m[i];

    // prefetch chunk 0: 8 float4 per thread, coalesced (8 threads span a row chunk)
    float4 P[8];
#pragma unroll
    for (int f = 0; f < 8; f++) {
        int idx = t + f * DR;
        int r = idx >> 3;
        int c4 = idx & 7;
        int gr = row0 + r;
        P[f] = (gr < NROWS) ? ((const float4*)(x + (size_t)gr * DIM))[c4]
                            : make_float4(0.f, 0.f, 0.f, 0.f);
    }

    float a0 = 0.0f, a1 = 0.0f, a2 = 0.0f, a3 = 0.0f;

    for (int cb = 0; cb < DIM / DCH; cb++) {
        // commit prefetched chunk to smem
#pragma unroll
        for (int f = 0; f < 8; f++) {
            int idx = t + f * DR;
            int r = idx >> 3;
            int c4 = idx & 7;
            buf[cb & 1][r][c4 * 4 + 0] = P[f].x;
            buf[cb & 1][r][c4 * 4 + 1] = P[f].y;
            buf[cb & 1][r][c4 * 4 + 2] = P[f].z;
            buf[cb & 1][r][c4 * 4 + 3] = P[f].w;
        }
        __syncthreads();
        // issue next chunk's loads before computing (overlaps DRAM latency)
        if (cb + 1 < DIM / DCH) {
#pragma unroll
            for (int f = 0; f < 8; f++) {
                int idx = t + f * DR;
                int r = idx >> 3;
                int c4 = idx & 7;
                int gr = row0 + r;
                P[f] = (gr < NROWS)
                     ? ((const float4*)(x + (size_t)gr * DIM + (cb + 1) * DCH))[c4]
                     : make_float4(0.f, 0.f, 0.f, 0.f);
            }
        }
        if (valid) {
            const float* tr = buf[cb & 1][t];
            const float* mc = ms + cb * DCH;
#pragma unroll
            for (int c = 0; c < DCH; c += 4) {
                a0 = __fmaf_rn(tr[c + 0], mc[c + 0], a0);
                a1 = __fmaf_rn(tr[c + 1], mc[c + 1], a1);
                a2 = __fmaf_rn(tr[c + 2], mc[c + 2], a2);
                a3 = __fmaf_rn(tr[c + 3], mc[c + 3], a3);
            }
        }
        __syncthreads();
    }

    float score = -CUDART_INF_F;
    if (valid) {
        float dot = __fadd_rn(__fadd_rn(a0, a1), __fadd_rn(a2, a3));
        score = __fadd_rn(__fdiv_rn(1.0f, dot), g_taken[row]);
    }
    sSc[t] = score;
    sIx[t] = row;
    __syncthreads();
    for (int off = DR / 2; off > 0; off >>= 1) {
        if (t < off) {
            float s = sSc[t + off];
            int  id = sIx[t + off];
            if (s > sSc[t] || (s == sSc[t] && id < sIx[t])) { sSc[t] = s; sIx[t] = id; }
        }
        __syncthreads();
    }
    if (t == 0)
        atomicMax(&g_best, pack_key(sSc[0], sIx[0]));
}

// -------- finalize: read packed winner, update taken state, reset key -------
__global__ void finalize_kernel(int k) {
    unsigned long long key = g_best;
    int w = (int)(0xffffffffu - (unsigned)(key & 0xffffffffu));
    g_sel[k] = w;
    float t = g_taken[w];
    g_taken[w] = __fadd_rn(t, -100000.0f);
    if (t == 0.0f) {
        g_remaining -= 1;
        int n = g_nTaken;
        int pos = n;
        while (pos > 0 && g_takenList[pos - 1] > w) {
            g_takenList[pos] = g_takenList[pos - 1];
            pos--;
        }
        g_takenList[pos] = w;
        g_nTaken = n + 1;
    }
    g_restartSeg = w >> 10;   // chain changes from row w onward
    g_best = 0ull;            // reset for next iteration
}

// -------- epilogue: rank sort (duplicate-safe), gather rows --------
__global__ void sortsel_kernel() {
    int t = threadIdx.x;            // 64 threads
    int v = g_sel[t];
    int r = 0;
    for (int j = 0; j < RNUM; j++) {
        int u = g_sel[j];
        r += (u < v) || (u == v && j < t);
    }
    g_selSorted[r] = v;
}

__global__ void gather_kernel(const float* __restrict__ x, float* __restrict__ out) {
    int row = g_selSorted[blockIdx.x];
    const float4* src = (const float4*)(x + (size_t)row * DIM);
    float4* dst = (float4*)(out + (size_t)blockIdx.x * DIM);
    dst[threadIdx.x] = src[threadIdx.x];   // 256 threads x float4 = 1024 floats
}

extern "C" void kernel_launch(void* const* d_in, const int* in_sizes, int n_in,
                              void* d_out, int out_size) {
    const float* x = (const float*)d_in[0];
    float* out = (float*)d_out;

    cudaFuncSetAttribute(colsum_kernel,
                         cudaFuncAttributeMaxDynamicSharedMemorySize, CS_SMEM);

    init_kernel<<<(NROWS + 255) / 256, 256>>>();

    for (int k = 0; k < RNUM; k++) {
        colsum_kernel<<<CS_BLOCKS, 256, CS_SMEM>>>(x);
        dots_argmax_kernel<<<DBLK, DR>>>(x);
        finalize_kernel<<<1, 1>>>(k);
    }

    sortsel_kernel<<<1, RNUM>>>();
    gather_kernel<<<RNUM, 256>>>(x, out);
}

// round 12
// speedup vs baseline: 1.3180x; 1.3180x over previous
#include <cuda_runtime.h>
#include <math_constants.h>
#include <cstdint>

#define NROWS 100000
#define DIM   1024
#define RNUM  64

#define SEG        1024
#define NSEG_CKPT  97          // boundaries at rows 1024..99328

// colsum pipeline (R10 measured-good config): 32 blocks x 32 cols,
// 256-row tiles, 4-stage cp.async ring
#define CS_BLOCKS 32
#define CS_COLS   32
#define CS_T      256
#define CS_S      4
#define CS_SMEM   (CS_S * CS_T * CS_COLS * 4)   // 128 KB dynamic

// dots: 128 rows per block, 32-col chunks, cp.async double-buffered
#define DR      128
#define DCH     32
#define DSTRIDE 36                       // 144B rows: 16B-aligned, 4-way read conflicts
#define DBLK ((NROWS + DR - 1) / DR)     // 782
#define NKEYS   8

// -------- scratch (no allocations allowed) --------
__device__ float g_ckpt[NSEG_CKPT][DIM];  // chain state after rows [0,(s+1)*SEG)
__device__ float g_m[DIM];
__device__ float g_taken[NROWS];
__device__ int   g_takenList[RNUM];       // sorted ascending, distinct taken rows
__device__ int   g_nTaken;
__device__ int   g_remaining;
__device__ int   g_restartSeg;            // first segment whose chain changed
__device__ unsigned long long g_bestK[NKEYS];  // packed (enc(score) << 32) | ~idx
__device__ int   g_sel[RNUM];
__device__ int   g_selSorted[RNUM];

// monotone float encoding; ties -> smaller idx wins via ~idx in low bits
__device__ __forceinline__ unsigned long long pack_key(float s, int idx) {
    unsigned b = __float_as_uint(s);
    b = (b & 0x80000000u) ? ~b : (b | 0x80000000u);
    return ((unsigned long long)b << 32) | (unsigned)(0xffffffffu - (unsigned)idx);
}

// -------- init (graph replays must fully reset state) --------
__global__ void init_kernel() {
    int i = blockIdx.x * blockDim.x + threadIdx.x;
    if (i < NROWS) g_taken[i] = 0.0f;
    if (i < NKEYS) g_bestK[i] = 0ull;
    if (i == 0) { g_remaining = NROWS; g_nTaken = 0; g_restartSeg = 0; }
}

__device__ __forceinline__ void cp_async16(uint32_t saddr, const float* gptr) {
    asm volatile("cp.async.ca.shared.global [%0], [%1], 16;" :: "r"(saddr), "l"(gptr));
}

// producers (threads 32..255): issue one 256-row x 32-col tile (2048 x 16B)
__device__ __forceinline__ void cs_issue(const float* __restrict__ x, uint32_t bufAddr,
                                         int rStart, int ti, int colBase, int t) {
    int r0 = rStart + ti * CS_T;
    int st = ti & (CS_S - 1);
    uint32_t stBase = bufAddr + (uint32_t)(st * CS_T * CS_COLS * 4);
    int p = t - 32;                       // 0..223
#pragma unroll 3
    for (int op = p; op < CS_T * 8; op += 224) {
        int row = op >> 3;
        int ch  = op & 7;
        int gr = r0 + row;
        if (gr < NROWS)
            cp_async16(stBase + (uint32_t)((row * CS_COLS + ch * 4) * 4),
                       x + (size_t)gr * DIM + colBase + ch * 4);
    }
}

// -------- colsum: bit-exact sequential fadd chain per column (validated R8-R10),
// warp-specialized: warps 1-7 produce via cp.async ring, warp 0 = 32 chains. --
__global__ void __launch_bounds__(256) colsum_kernel(const float* __restrict__ x) {
    extern __shared__ float buf[];               // [CS_S][CS_T][CS_COLS]
    __shared__ int sList[RNUM];
    __shared__ int sMeta[3];

    int t = threadIdx.x;
    if (t == 0) { sMeta[0] = g_nTaken; sMeta[1] = g_restartSeg; sMeta[2] = g_remaining; }
    __syncthreads();
    int sN = sMeta[0], sSeg = sMeta[1], sRem = sMeta[2];
    if (t < RNUM && t < sN) sList[t] = g_takenList[t];
    __syncthreads();

    int colBase = blockIdx.x * CS_COLS;
    int rStart = sSeg << 10;
    int ntiles = (NROWS - rStart + CS_T - 1) / CS_T;

    uint32_t bufAddr = (uint32_t)__cvta_generic_to_shared(buf);
    bool producer = (t >= 32);

    // prologue: tiles 0..2 in flight
#pragma unroll
    for (int ti = 0; ti < CS_S - 1; ti++) {
        if (producer && ti < ntiles) cs_issue(x, bufAddr, rStart, ti, colBase, t);
        asm volatile("cp.async.commit_group;");
    }

    // consumer chain state (lanes 0..31 of warp 0)
    float acc = 0.0f;
    int p = 0, nxt = 0x7fffffff;
    if (t < CS_COLS) {
        if (sSeg > 0) acc = g_ckpt[sSeg - 1][colBase + t];
        while (p < sN && sList[p] < rStart) p++;
        nxt = (p < sN) ? sList[p] : 0x7fffffff;
    }

    for (int i = 0; i < ntiles; i++) {
        asm volatile("cp.async.wait_group 2;");  // tile i complete
        __syncthreads();
        if (producer && (i + CS_S - 1) < ntiles)
            cs_issue(x, bufAddr, rStart, i + CS_S - 1, colBase, t);
        asm volatile("cp.async.commit_group;");

        if (t < CS_COLS) {
            const float* s = buf + (i & (CS_S - 1)) * CS_T * CS_COLS + t;
            int r0 = rStart + i * CS_T;
            int nr = min(CS_T, NROWS - r0);
            bool slow = (nr < CS_T) || (nxt < r0 + nr);
            if (!slow) {
                // pure chain, software-pipelined 16-row register batches
                float v0[16], v1[16];
#define LOADB(arr, b) { _Pragma("unroll") \
    for (int j = 0; j < 16; j++) arr[j] = s[(((b) << 4) + j) * CS_COLS]; }
#define CHAINB(arr) { _Pragma("unroll") \
    for (int j = 0; j < 16; j++) acc = __fadd_rn(acc, arr[j]); }
                LOADB(v0, 0)
#pragma unroll
                for (int b = 0; b < CS_T / 16; b++) {
                    if (b & 1) { if (b + 1 < CS_T / 16) LOADB(v0, b + 1) CHAINB(v1) }
                    else       { if (b + 1 < CS_T / 16) LOADB(v1, b + 1) CHAINB(v0) }
                }
                if (((r0 + CS_T) & (SEG - 1)) == 0)
                    g_ckpt[((r0 + CS_T) >> 10) - 1][colBase + t] = acc;
            } else {
                for (int j = 0; j < nr; j++) {
                    int r = r0 + j;
                    float v = s[j * CS_COLS];
                    if (r == nxt) { p++; nxt = (p < sN) ? sList[p] : 0x7fffffff; }
                    else acc = __fadd_rn(acc, v);
                    if (((r + 1) & (SEG - 1)) == 0)
                        g_ckpt[((r + 1) >> 10) - 1][colBase + t] = acc;
                }
            }
        }
        __syncthreads();
    }
    asm volatile("cp.async.wait_group 0;");
    if (t < CS_COLS)
        g_m[colBase + t] = __fdiv_rn(acc, (float)sRem);
}

// -------- dots + argmax: Eigen 4-chain FMA order (validated R8-R11),
// cp.async double-buffered streaming; block argmax -> spread atomicMax keys. --
__global__ void __launch_bounds__(DR) dots_argmax_kernel(const float* __restrict__ x) {
    __shared__ float buf[2][DR][DSTRIDE];    // 36.9 KB
    __shared__ float ms[DIM];                // 4 KB
    __shared__ float sSc[DR];
    __shared__ int   sIx[DR];

    int t = threadIdx.x;
    int row0 = blockIdx.x * DR;
    int row = row0 + t;
    bool valid = row < NROWS;

    for (int i = t; i < DIM; i += DR) ms[i] = g_m[i];

    uint32_t bufAddr = (uint32_t)__cvta_generic_to_shared(&buf[0][0][0]);

    // issue one chunk: 128 rows x 32 cols = 1024 x 16B, 8 per thread, coalesced
#define D_ISSUE(cb) {                                                          \
        uint32_t base = bufAddr + (uint32_t)(((cb) & 1) * DR * DSTRIDE * 4);   \
        _Pragma("unroll")                                                      \
        for (int f = 0; f < 8; f++) {                                          \
            int op = t + f * DR;                                               \
            int r = op >> 3;                                                   \
            int ch = op & 7;                                                   \
            int gr = row0 + r;                                                 \
            if (gr < NROWS)                                                    \
                cp_async16(base + (uint32_t)((r * DSTRIDE + ch * 4) * 4),      \
                           x + (size_t)gr * DIM + (cb) * DCH + ch * 4);        \
        }                                                                      \
    }

    D_ISSUE(0)
    asm volatile("cp.async.commit_group;");

    float a0 = 0.0f, a1 = 0.0f, a2 = 0.0f, a3 = 0.0f;

    for (int cb = 0; cb < DIM / DCH; cb++) {
        if (cb + 1 < DIM / DCH) D_ISSUE(cb + 1)
        asm volatile("cp.async.commit_group;");
        asm volatile("cp.async.wait_group 1;");  // chunk cb resident
        __syncthreads();
        if (valid) {
            const float* tr = buf[cb & 1][t];
            const float* mc = ms + cb * DCH;
#pragma unroll
            for (int c = 0; c < DCH; c += 4) {
                a0 = __fmaf_rn(tr[c + 0], mc[c + 0], a0);
                a1 = __fmaf_rn(tr[c + 1], mc[c + 1], a1);
                a2 = __fmaf_rn(tr[c + 2], mc[c + 2], a2);
                a3 = __fmaf_rn(tr[c + 3], mc[c + 3], a3);
            }
        }
        __syncthreads();                         // compute done before reusing buffer
    }

    float score = -CUDART_INF_F;
    if (valid) {
        float dot = __fadd_rn(__fadd_rn(a0, a1), __fadd_rn(a2, a3));
        score = __fadd_rn(__fdiv_rn(1.0f, dot), g_taken[row]);
    }
    sSc[t] = score;
    sIx[t] = row;
    __syncthreads();
    for (int off = DR / 2; off > 0; off >>= 1) {
        if (t < off) {
            float s = sSc[t + off];
            int  id = sIx[t + off];
            if (s > sSc[t] || (s == sSc[t] && id < sIx[t])) { sSc[t] = s; sIx[t] = id; }
        }
        __syncthreads();
    }
    if (t == 0)
        atomicMax(&g_bestK[blockIdx.x & (NKEYS - 1)], pack_key(sSc[0], sIx[0]));
}

// -------- finalize: reduce NKEYS packed winners, update taken state ---------
__global__ void finalize_kernel(int k) {
    unsigned long long key = 0ull;
#pragma unroll
    for (int i = 0; i < NKEYS; i++) {
        unsigned long long v = g_bestK[i];
        if (v > key) key = v;
        g_bestK[i] = 0ull;                 // reset for next iteration
    }
    int w = (int)(0xffffffffu - (unsigned)(key & 0xffffffffu));
    g_sel[k] = w;
    float t = g_taken[w];
    g_taken[w] = __fadd_rn(t, -100000.0f);
    if (t == 0.0f) {
        g_remaining -= 1;
        int n = g_nTaken;
        int pos = n;
        while (pos > 0 && g_takenList[pos - 1] > w) {
            g_takenList[pos] = g_takenList[pos - 1];
            pos--;
        }
        g_takenList[pos] = w;
        g_nTaken = n + 1;
    }
    g_restartSeg = w >> 10;   // chain changes from row w onward
}

// -------- epilogue: rank sort (duplicate-safe), gather rows --------
__global__ void sortsel_kernel() {
    int t = threadIdx.x;            // 64 threads
    int v = g_sel[t];
    int r = 0;
    for (int j = 0; j < RNUM; j++) {
        int u = g_sel[j];
        r += (u < v) || (u == v && j < t);
    }
    g_selSorted[r] = v;
}

__global__ void gather_kernel(const float* __restrict__ x, float* __restrict__ out) {
    int row = g_selSorted[blockIdx.x];
    const float4* src = (const float4*)(x + (size_t)row * DIM);
    float4* dst = (float4*)(out + (size_t)blockIdx.x * DIM);
    dst[threadIdx.x] = src[threadIdx.x];   // 256 threads x float4 = 1024 floats
}

extern "C" void kernel_launch(void* const* d_in, const int* in_sizes, int n_in,
                              void* d_out, int out_size) {
    const float* x = (const float*)d_in[0];
    float* out = (float*)d_out;

    cudaFuncSetAttribute(colsum_kernel,
                         cudaFuncAttributeMaxDynamicSharedMemorySize, CS_SMEM);

    init_kernel<<<(NROWS + 255) / 256, 256>>>();

    for (int k = 0; k < RNUM; k++) {
        colsum_kernel<<<CS_BLOCKS, 256, CS_SMEM>>>(x);
        dots_argmax_kernel<<<DBLK, DR>>>(x);
        finalize_kernel<<<1, 1>>>(k);
    }

    sortsel_kernel<<<1, RNUM>>>();
    gather_kernel<<<RNUM, 256>>>(x, out);
}